// round 2
// baseline (speedup 1.0000x reference)
#include <cuda_runtime.h>

// ---------------- problem constants ----------------
#define PN    8192
#define WD    256
#define HD    256
#define TANXc 0.5f
#define TANYc 0.5f
#define FXc   256.0f
#define FYc   256.0f
#define RCAP  8192      // per-region list capacity (cannot overflow: <= PN)

typedef unsigned long long u64;

// ---------------- scratch ----------------
__device__ float4 g_pe_u[PN];
__device__ float4 g_co_u[PN];
__device__ float4 g_cl_u[PN];
__device__ u64    g_keys[PN];
__device__ float4 g_pe[PN];
__device__ float4 g_co[PN];
__device__ float4 g_cl[PN];
// 64 regions of 32x32 px, depth-ordered compacted lists
__device__ float4 g_rpe[64 * RCAP];
__device__ float4 g_rco[64 * RCAP];
__device__ float4 g_rcl[64 * RCAP];
__device__ int    g_rcnt[64];

__device__ __forceinline__ void cxs(u64& x, u64& y, bool up) {
    if ((x > y) == up) { u64 t = x; x = y; y = t; }
}

// ---------------- per-gaussian preprocess (returns sort key) ----------------
__device__ __forceinline__ u64 preprocess_one(int i,
    const float* __restrict__ means, const float* __restrict__ cols,
    const float* __restrict__ ops, const float* __restrict__ scales,
    const float* __restrict__ rots, const float* __restrict__ Vm,
    const float* __restrict__ Pr)
{
    float mx = means[3*i+0], my = means[3*i+1], mz = means[3*i+2];

    float pv0 = mx*Vm[0] + my*Vm[4] + mz*Vm[8]  + Vm[12];
    float pv1 = mx*Vm[1] + my*Vm[5] + mz*Vm[9]  + Vm[13];
    float pv2 = mx*Vm[2] + my*Vm[6] + mz*Vm[10] + Vm[14];

    float ph0 = mx*Pr[0] + my*Pr[4] + mz*Pr[8]  + Pr[12];
    float ph1 = mx*Pr[1] + my*Pr[5] + mz*Pr[9]  + Pr[13];
    float ph3 = mx*Pr[3] + my*Pr[7] + mz*Pr[11] + Pr[15];
    float invw = 1.0f / (ph3 + 1e-7f);
    float m2x = ((ph0*invw + 1.0f) * (float)WD - 1.0f) * 0.5f;
    float m2y = ((ph1*invw + 1.0f) * (float)HD - 1.0f) * 0.5f;

    float qr = rots[4*i+0], qx = rots[4*i+1], qy = rots[4*i+2], qz = rots[4*i+3];
    float qn = sqrtf(qr*qr + qx*qx + qy*qy + qz*qz);
    qr /= qn; qx /= qn; qy /= qn; qz /= qn;
    float R[3][3];
    R[0][0] = 1.0f - 2.0f*(qy*qy + qz*qz); R[0][1] = 2.0f*(qx*qy - qr*qz); R[0][2] = 2.0f*(qx*qz + qr*qy);
    R[1][0] = 2.0f*(qx*qy + qr*qz); R[1][1] = 1.0f - 2.0f*(qx*qx + qz*qz); R[1][2] = 2.0f*(qy*qz - qr*qx);
    R[2][0] = 2.0f*(qx*qz - qr*qy); R[2][1] = 2.0f*(qy*qz + qr*qx); R[2][2] = 1.0f - 2.0f*(qx*qx + qy*qy);

    float s0 = scales[3*i+0], s1 = scales[3*i+1], s2 = scales[3*i+2];
    float sq0 = s0*s0, sq1 = s1*s1, sq2 = s2*s2;

    float Sg[3][3];
    #pragma unroll
    for (int r = 0; r < 3; r++)
        #pragma unroll
        for (int c = 0; c < 3; c++)
            Sg[r][c] = R[r][0]*sq0*R[c][0] + R[r][1]*sq1*R[c][1] + R[r][2]*sq2*R[c][2];

    float Mt[3][3], Cc[3][3];
    #pragma unroll
    for (int r = 0; r < 3; r++)
        #pragma unroll
        for (int k = 0; k < 3; k++)
            Mt[r][k] = Vm[0*4+r]*Sg[0][k] + Vm[1*4+r]*Sg[1][k] + Vm[2*4+r]*Sg[2][k];
    #pragma unroll
    for (int r = 0; r < 3; r++)
        #pragma unroll
        for (int l = 0; l < 3; l++)
            Cc[r][l] = Mt[r][0]*Vm[0*4+l] + Mt[r][1]*Vm[1*4+l] + Mt[r][2]*Vm[2*4+l];

    float tz  = pv2;
    float itz = 1.0f / tz;
    float limx = 1.3f * TANXc, limy = 1.3f * TANYc;
    float txc = fminf(limx, fmaxf(-limx, pv0*itz)) * tz;
    float tyc = fminf(limy, fmaxf(-limy, pv1*itz)) * tz;
    float J00 = FXc*itz, J02 = -FXc*txc*itz*itz;
    float J11 = FYc*itz, J12 = -FYc*tyc*itz*itz;

    float T00 = J00*Cc[0][0] + J02*Cc[2][0];
    float T01 = J00*Cc[0][1] + J02*Cc[2][1];
    float T02 = J00*Cc[0][2] + J02*Cc[2][2];
    float T11 = J11*Cc[1][1] + J12*Cc[2][1];
    float T12 = J11*Cc[1][2] + J12*Cc[2][2];
    float c00 = T00*J00 + T02*J02;
    float c01 = T01*J11 + T02*J12;
    float c11 = T11*J11 + T12*J12;

    float a = c00 + 0.3f, b = c01, c = c11 + 0.3f;
    float det  = a*c - b*b;
    float idet = 1.0f / det;
    float A  = c*idet, B = -b*idet, C2 = a*idet;

    float o   = ops[i];
    float tau = 2.0f * logf(255.0f * o);
    float tq  = fmaxf(tau, 0.0f);
    float ex  = sqrtf(tq * a) + 1.0f;
    float ey  = sqrtf(tq * c) + 1.0f;
    if (tau <= 0.0f) { ex = -1e30f; ey = -1e30f; }

    g_pe_u[i] = make_float4(m2x, m2y, ex, ey);
    g_co_u[i] = make_float4(A, B, C2, o);
    g_cl_u[i] = make_float4(cols[3*i+0], cols[3*i+1], cols[3*i+2], 0.0f);
    return ((u64)__float_as_uint(pv2) << 32) | (unsigned)i;
}

// ---------------- fused preprocess + local bitonic sort of 2048-spans ----------------
__global__ __launch_bounds__(1024) void pre_sort2048(
    const float* __restrict__ means, const float* __restrict__ cols,
    const float* __restrict__ ops, const float* __restrict__ scales,
    const float* __restrict__ rots, const float* __restrict__ Vm,
    const float* __restrict__ Pr)
{
    __shared__ u64 sk[2048];
    const int base = blockIdx.x * 2048;
    const int t = threadIdx.x;
    sk[t]        = preprocess_one(base + t,        means, cols, ops, scales, rots, Vm, Pr);
    sk[t + 1024] = preprocess_one(base + t + 1024, means, cols, ops, scales, rots, Vm, Pr);
    __syncthreads();

    for (int k = 2; k <= 2048; k <<= 1) {
        int j = k >> 1;
        while (j >= 2) {           // fused (j, j/2) quad pass
            int j2 = j >> 1;
            if (t < 512) {
                int q  = t;
                int i0 = ((q & ~(j2 - 1)) << 2) | (q & (j2 - 1));
                bool up = (((base + i0) & k) == 0);
                u64 a = sk[i0], b = sk[i0 | j2], c = sk[i0 | j], d = sk[i0 | j | j2];
                cxs(a, c, up); cxs(b, d, up);   // layer j
                cxs(a, b, up); cxs(c, d, up);   // layer j/2
                sk[i0] = a; sk[i0 | j2] = b; sk[i0 | j] = c; sk[i0 | j | j2] = d;
            }
            __syncthreads();
            j >>= 2;
        }
        if (j == 1) {              // leftover single layer
            int i = t << 1;
            bool up = (((base + i) & k) == 0);
            u64 x = sk[i], y = sk[i + 1];
            if ((x > y) == up) { sk[i] = y; sk[i + 1] = x; }
            __syncthreads();
        }
    }
    g_keys[base + t]        = sk[t];
    g_keys[base + t + 1024] = sk[t + 1024];
}

// ---------------- k=4096 merge: 2 blocks, full window in smem ----------------
__global__ __launch_bounds__(1024) void merge4096()
{
    __shared__ u64 sk[4096];
    const int base = blockIdx.x * 4096;
    const int t = threadIdx.x;
    #pragma unroll
    for (int p = 0; p < 4; p++) sk[t + p * 1024] = g_keys[base + t + p * 1024];
    __syncthreads();

    const int k = 4096;
    int j = 2048;
    while (j >= 2) {
        int j2 = j >> 1;
        int q  = t;                      // 1024 quads
        int i0 = ((q & ~(j2 - 1)) << 2) | (q & (j2 - 1));
        bool up = (((base + i0) & k) == 0);
        u64 a = sk[i0], b = sk[i0 | j2], c = sk[i0 | j], d = sk[i0 | j | j2];
        cxs(a, c, up); cxs(b, d, up);
        cxs(a, b, up); cxs(c, d, up);
        sk[i0] = a; sk[i0 | j2] = b; sk[i0 | j] = c; sk[i0 | j | j2] = d;
        __syncthreads();
        j >>= 2;
    }   // j sequence 2048,512,128,32,8,2 covers all 12 layers

    #pragma unroll
    for (int p = 0; p < 4; p++) g_keys[base + t + p * 1024] = sk[t + p * 1024];
}

// ---------------- k=8192 merge (1 block, 64KB smem) + fused gather ----------------
__global__ __launch_bounds__(1024) void merge8192()
{
    extern __shared__ u64 sk[];
    const int t = threadIdx.x;
    #pragma unroll
    for (int p = 0; p < 8; p++) sk[t + p * 1024] = g_keys[t + p * 1024];
    __syncthreads();

    int j = 4096;                        // ascending (i & 8192 == 0 for all i)
    while (j >= 2) {
        int j2 = j >> 1;
        #pragma unroll
        for (int p = 0; p < 2; p++) {    // 2048 quads / 1024 threads
            int q  = t + p * 1024;
            int i0 = ((q & ~(j2 - 1)) << 2) | (q & (j2 - 1));
            u64 a = sk[i0], b = sk[i0 | j2], c = sk[i0 | j], d = sk[i0 | j | j2];
            cxs(a, c, true); cxs(b, d, true);
            cxs(a, b, true); cxs(c, d, true);
            sk[i0] = a; sk[i0 | j2] = b; sk[i0 | j] = c; sk[i0 | j | j2] = d;
        }
        __syncthreads();
        j >>= 2;
    }   // j sequence 4096,1024,256,64,16,4 -> leaves j=1
    #pragma unroll
    for (int p = 0; p < 2; p++) {        // final j=1 layer
        int i = (t + p * 1024) << 1;
        u64 x = sk[i], y = sk[i + 1];
        if (x > y) { sk[i] = y; sk[i + 1] = x; }
    }
    __syncthreads();

    // fused gather into sorted SoA
    #pragma unroll
    for (int p = 0; p < 8; p++) {
        int i = t + p * 1024;
        int s = (int)(sk[i] & 0xFFFFFFFFu);
        g_pe[i] = g_pe_u[s];
        g_co[i] = g_co_u[s];
        g_cl[i] = g_cl_u[s];
    }
}

// ---------------- bin sorted gaussians into 64 region lists (32x32 px) ----------------
__global__ __launch_bounds__(256) void bin_kernel()
{
    const int r = blockIdx.x;
    const float xmin = (float)((r & 7) * 32),  xmax = xmin + 31.0f;
    const float ymin = (float)((r >> 3) * 32), ymax = ymin + 31.0f;
    const int tid = threadIdx.x, wid = tid >> 5, lane = tid & 31;
    const int obase = r * RCAP;

    __shared__ int s_wcnt[8];
    __shared__ int s_woff[8];
    __shared__ int s_total;

    int outbase = 0;
    for (int chunk = 0; chunk < PN / 256; chunk++) {
        int g = chunk * 256 + tid;
        float4 pe = g_pe[g];
        bool hit = (pe.x + pe.z >= xmin) && (pe.x - pe.z <= xmax) &&
                   (pe.y + pe.w >= ymin) && (pe.y - pe.w <= ymax);
        unsigned bal = __ballot_sync(0xffffffffu, hit);
        if (lane == 0) s_wcnt[wid] = __popc(bal);
        __syncthreads();
        if (tid == 0) {
            int s = 0;
            #pragma unroll
            for (int w = 0; w < 8; w++) { s_woff[w] = s; s += s_wcnt[w]; }
            s_total = s;
        }
        __syncthreads();
        if (hit) {
            int slot = outbase + s_woff[wid] + __popc(bal & ((1u << lane) - 1u));
            g_rpe[obase + slot] = pe;
            g_rco[obase + slot] = g_co[g];
            g_rcl[obase + slot] = g_cl[g];
        }
        outbase += s_total;
    }
    if (tid == 0) g_rcnt[r] = outbase;
}

// ---------------- tiled rasterizer over region lists ----------------
__global__ __launch_bounds__(256) void raster_kernel(const float* __restrict__ bg,
                                                     float* __restrict__ out)
{
    const int tx = threadIdx.x, ty = threadIdx.y;
    const int tid = ty * 16 + tx;
    const int pxi = blockIdx.x * 16 + tx;
    const int pyi = blockIdx.y * 16 + ty;
    const float pxf = (float)pxi, pyf = (float)pyi;
    const float xmin = (float)(blockIdx.x * 16), xmax = xmin + 15.0f;
    const float ymin = (float)(blockIdx.y * 16), ymax = ymin + 15.0f;

    const int r = (int)(blockIdx.y >> 1) * 8 + (int)(blockIdx.x >> 1);
    const int n = g_rcnt[r];
    const int obase = r * RCAP;

    __shared__ float2 s_xy[256];
    __shared__ float4 s_co[256];
    __shared__ float4 s_cl[256];
    __shared__ int s_wcnt[8];
    __shared__ int s_woff[8];
    __shared__ int s_total;

    float T = 1.0f;
    float ar = 0.0f, ag = 0.0f, ab = 0.0f;
    bool alive = true;

    const int wid = tid >> 5, lane = tid & 31;

    for (int start = 0; start < n; start += 256) {
        int g = start + tid;
        bool inb = (g < n);
        float4 pe = inb ? g_rpe[obase + g] : make_float4(0.f, 0.f, -1e30f, -1e30f);
        bool hit = (pe.x + pe.z >= xmin) && (pe.x - pe.z <= xmax) &&
                   (pe.y + pe.w >= ymin) && (pe.y - pe.w <= ymax);
        unsigned bal = __ballot_sync(0xffffffffu, hit);
        if (lane == 0) s_wcnt[wid] = __popc(bal);
        __syncthreads();
        if (tid == 0) {
            int s = 0;
            #pragma unroll
            for (int w = 0; w < 8; w++) { s_woff[w] = s; s += s_wcnt[w]; }
            s_total = s;
        }
        __syncthreads();
        if (hit) {
            int slot = s_woff[wid] + __popc(bal & ((1u << lane) - 1u));
            s_xy[slot] = make_float2(pe.x, pe.y);
            s_co[slot] = g_rco[obase + g];
            s_cl[slot] = g_rcl[obase + g];
        }
        __syncthreads();
        int cnt = s_total;

        if (alive) {
            for (int jj = 0; jj < cnt; jj++) {
                float2 xy = s_xy[jj];
                float4 co = s_co[jj];
                float dx = xy.x - pxf;
                float dy = xy.y - pyf;
                float power = -0.5f * (co.x*dx*dx + co.z*dy*dy) - co.y*dx*dy;
                if (power > 0.0f) continue;
                float raw = co.w * __expf(power);
                if (raw < (1.0f / 255.0f)) continue;
                float alpha = fminf(0.99f, raw);
                float4 cl = s_cl[jj];
                float wgt = alpha * T;
                ar += wgt * cl.x;
                ag += wgt * cl.y;
                ab += wgt * cl.z;
                T *= (1.0f - alpha);
                if (T < 1e-6f) { alive = false; break; }
            }
        }
        int nalive = __syncthreads_count(alive ? 1 : 0);
        if (nalive == 0) break;
    }

    int pid = pyi * WD + pxi;
    out[pid]           = ar + T * bg[0];
    out[HD*WD + pid]   = ag + T * bg[1];
    out[2*HD*WD + pid] = ab + T * bg[2];
}

// ---------------- launch ----------------
extern "C" void kernel_launch(void* const* d_in, const int* in_sizes, int n_in,
                              void* d_out, int out_size)
{
    const float* means  = (const float*)d_in[0];
    const float* cols   = (const float*)d_in[1];
    const float* ops    = (const float*)d_in[2];
    const float* scales = (const float*)d_in[3];
    const float* rots   = (const float*)d_in[4];
    const float* bg     = (const float*)d_in[5];
    const float* Vm     = (const float*)d_in[6];
    const float* Pr     = (const float*)d_in[7];
    float* out = (float*)d_out;

    cudaFuncSetAttribute(merge8192, cudaFuncAttributeMaxDynamicSharedMemorySize, 65536);

    pre_sort2048<<<PN/2048, 1024>>>(means, cols, ops, scales, rots, Vm, Pr);
    merge4096<<<2, 1024>>>();
    merge8192<<<1, 1024, 65536>>>();
    bin_kernel<<<64, 256>>>();
    dim3 grid(WD/16, HD/16), block(16, 16);
    raster_kernel<<<grid, block>>>(bg, out);
}

// round 3
// speedup vs baseline: 1.0425x; 1.0425x over previous
#include <cuda_runtime.h>

// ---------------- problem constants ----------------
#define PN    8192
#define WD    256
#define HD    256
#define TANXc 0.5f
#define TANYc 0.5f
#define FXc   256.0f
#define FYc   256.0f
#define RCAP  8192      // per-region capacity (<= PN, cannot overflow)

typedef unsigned long long u64;

// ---------------- scratch ----------------
__device__ float4 g_pe_u[PN];          // unsorted: mean2d.xy, ext xy
__device__ float4 g_co_u[PN];          // unsorted: conic A,B,C, opacity
__device__ float4 g_cl_u[PN];          // unsorted: color
__device__ u64    g_rkey[64 * RCAP];   // per-region unsorted keys
__device__ int    g_rcnt[64];          // per-region counts (atomic)
__device__ float4 g_rpe[64 * RCAP];    // per-region depth-sorted payloads
__device__ float4 g_rco[64 * RCAP];
__device__ float4 g_rcl[64 * RCAP];

// ---------------- zero the atomic counters (graph replays) ----------------
__global__ void zero_kernel()
{
    g_rcnt[threadIdx.x] = 0;
}

// ---------------- preprocess + direct region binning ----------------
__global__ __launch_bounds__(256) void preprocess_kernel(
    const float* __restrict__ means, const float* __restrict__ cols,
    const float* __restrict__ ops, const float* __restrict__ scales,
    const float* __restrict__ rots, const float* __restrict__ Vm,
    const float* __restrict__ Pr)
{
    int i = blockIdx.x * blockDim.x + threadIdx.x;
    if (i >= PN) return;

    float mx = means[3*i+0], my = means[3*i+1], mz = means[3*i+2];

    float pv0 = mx*Vm[0] + my*Vm[4] + mz*Vm[8]  + Vm[12];
    float pv1 = mx*Vm[1] + my*Vm[5] + mz*Vm[9]  + Vm[13];
    float pv2 = mx*Vm[2] + my*Vm[6] + mz*Vm[10] + Vm[14];

    float ph0 = mx*Pr[0] + my*Pr[4] + mz*Pr[8]  + Pr[12];
    float ph1 = mx*Pr[1] + my*Pr[5] + mz*Pr[9]  + Pr[13];
    float ph3 = mx*Pr[3] + my*Pr[7] + mz*Pr[11] + Pr[15];
    float invw = 1.0f / (ph3 + 1e-7f);
    float m2x = ((ph0*invw + 1.0f) * (float)WD - 1.0f) * 0.5f;
    float m2y = ((ph1*invw + 1.0f) * (float)HD - 1.0f) * 0.5f;

    float qr = rots[4*i+0], qx = rots[4*i+1], qy = rots[4*i+2], qz = rots[4*i+3];
    float qn = sqrtf(qr*qr + qx*qx + qy*qy + qz*qz);
    qr /= qn; qx /= qn; qy /= qn; qz /= qn;
    float R[3][3];
    R[0][0] = 1.0f - 2.0f*(qy*qy + qz*qz); R[0][1] = 2.0f*(qx*qy - qr*qz); R[0][2] = 2.0f*(qx*qz + qr*qy);
    R[1][0] = 2.0f*(qx*qy + qr*qz); R[1][1] = 1.0f - 2.0f*(qx*qx + qz*qz); R[1][2] = 2.0f*(qy*qz - qr*qx);
    R[2][0] = 2.0f*(qx*qz - qr*qy); R[2][1] = 2.0f*(qy*qz + qr*qx); R[2][2] = 1.0f - 2.0f*(qx*qx + qy*qy);

    float s0 = scales[3*i+0], s1 = scales[3*i+1], s2 = scales[3*i+2];
    float sq0 = s0*s0, sq1 = s1*s1, sq2 = s2*s2;

    float Sg[3][3];
    #pragma unroll
    for (int r = 0; r < 3; r++)
        #pragma unroll
        for (int c = 0; c < 3; c++)
            Sg[r][c] = R[r][0]*sq0*R[c][0] + R[r][1]*sq1*R[c][1] + R[r][2]*sq2*R[c][2];

    float Mt[3][3], Cc[3][3];
    #pragma unroll
    for (int r = 0; r < 3; r++)
        #pragma unroll
        for (int k = 0; k < 3; k++)
            Mt[r][k] = Vm[0*4+r]*Sg[0][k] + Vm[1*4+r]*Sg[1][k] + Vm[2*4+r]*Sg[2][k];
    #pragma unroll
    for (int r = 0; r < 3; r++)
        #pragma unroll
        for (int l = 0; l < 3; l++)
            Cc[r][l] = Mt[r][0]*Vm[0*4+l] + Mt[r][1]*Vm[1*4+l] + Mt[r][2]*Vm[2*4+l];

    float tz  = pv2;
    float itz = 1.0f / tz;
    float limx = 1.3f * TANXc, limy = 1.3f * TANYc;
    float txc = fminf(limx, fmaxf(-limx, pv0*itz)) * tz;
    float tyc = fminf(limy, fmaxf(-limy, pv1*itz)) * tz;
    float J00 = FXc*itz, J02 = -FXc*txc*itz*itz;
    float J11 = FYc*itz, J12 = -FYc*tyc*itz*itz;

    float T00 = J00*Cc[0][0] + J02*Cc[2][0];
    float T01 = J00*Cc[0][1] + J02*Cc[2][1];
    float T02 = J00*Cc[0][2] + J02*Cc[2][2];
    float T11 = J11*Cc[1][1] + J12*Cc[2][1];
    float T12 = J11*Cc[1][2] + J12*Cc[2][2];
    float c00 = T00*J00 + T02*J02;
    float c01 = T01*J11 + T02*J12;
    float c11 = T11*J11 + T12*J12;

    float a = c00 + 0.3f, b = c01, c = c11 + 0.3f;
    float det  = a*c - b*b;
    float idet = 1.0f / det;
    float A  = c*idet, B = -b*idet, C2 = a*idet;

    float o   = ops[i];
    float tau = 2.0f * logf(255.0f * o);
    float tq  = fmaxf(tau, 0.0f);
    float ex  = sqrtf(tq * a) + 1.0f;
    float ey  = sqrtf(tq * c) + 1.0f;

    g_pe_u[i] = make_float4(m2x, m2y, ex, ey);
    g_co_u[i] = make_float4(A, B, C2, o);
    g_cl_u[i] = make_float4(cols[3*i+0], cols[3*i+1], cols[3*i+2], 0.0f);

    if (tau <= 0.0f) return;   // alpha can never reach 1/255 anywhere

    // exact covered 32px-region span (conservative by <=1 region; fine test in raster)
    int rx0 = max(0, (int)floorf((m2x - ex - 31.0f) * (1.0f / 32.0f)));
    int rx1 = min(7, (int)floorf((m2x + ex)          * (1.0f / 32.0f)));
    int ry0 = max(0, (int)floorf((m2y - ey - 31.0f) * (1.0f / 32.0f)));
    int ry1 = min(7, (int)floorf((m2y + ey)          * (1.0f / 32.0f)));
    if (rx0 > rx1 || ry0 > ry1) return;

    u64 key = ((u64)__float_as_uint(pv2) << 32) | (unsigned)i;  // pv2>0: bit-monotonic
    for (int ry = ry0; ry <= ry1; ry++)
        for (int rx = rx0; rx <= rx1; rx++) {
            int r = ry * 8 + rx;
            int pos = atomicAdd(&g_rcnt[r], 1);
            g_rkey[r * RCAP + pos] = key;
        }
}

// ---------------- per-region depth sort (64 independent blocks) + gather ----------------
__global__ __launch_bounds__(256) void region_sort_kernel()
{
    extern __shared__ u64 sk[];
    const int r = blockIdx.x;
    const int t = threadIdx.x;
    const int n = g_rcnt[r];
    if (n == 0) return;

    int m = 2;
    while (m < n) m <<= 1;

    for (int i = t; i < m; i += 256)
        sk[i] = (i < n) ? g_rkey[r * RCAP + i] : ~0ull;
    __syncthreads();

    for (int k = 2; k <= m; k <<= 1) {
        for (int j = k >> 1; j > 0; j >>= 1) {
            for (int p = t; p < (m >> 1); p += 256) {
                int i  = ((p & ~(j - 1)) << 1) | (p & (j - 1));
                bool up = ((i & k) == 0);
                u64 x = sk[i], y = sk[i | j];
                if ((x > y) == up) { sk[i] = y; sk[i | j] = x; }
            }
            __syncthreads();
        }
    }

    // gather payloads in depth order
    for (int i = t; i < n; i += 256) {
        int s = (int)(sk[i] & 0xFFFFFFFFu);
        g_rpe[r * RCAP + i] = g_pe_u[s];
        g_rco[r * RCAP + i] = g_co_u[s];
        g_rcl[r * RCAP + i] = g_cl_u[s];
    }
}

// ---------------- tiled rasterizer over region lists ----------------
__global__ __launch_bounds__(256) void raster_kernel(const float* __restrict__ bg,
                                                     float* __restrict__ out)
{
    const int tx = threadIdx.x, ty = threadIdx.y;
    const int tid = ty * 16 + tx;
    const int pxi = blockIdx.x * 16 + tx;
    const int pyi = blockIdx.y * 16 + ty;
    const float pxf = (float)pxi, pyf = (float)pyi;
    const float xmin = (float)(blockIdx.x * 16), xmax = xmin + 15.0f;
    const float ymin = (float)(blockIdx.y * 16), ymax = ymin + 15.0f;

    const int r = (int)(blockIdx.y >> 1) * 8 + (int)(blockIdx.x >> 1);
    const int n = g_rcnt[r];
    const int obase = r * RCAP;

    __shared__ float2 s_xy[256];
    __shared__ float4 s_co[256];
    __shared__ float4 s_cl[256];
    __shared__ int s_wcnt[8];
    __shared__ int s_woff[8];
    __shared__ int s_total;

    float T = 1.0f;
    float ar = 0.0f, ag = 0.0f, ab = 0.0f;
    bool alive = true;

    const int wid = tid >> 5, lane = tid & 31;

    for (int start = 0; start < n; start += 256) {
        int g = start + tid;
        bool inb = (g < n);
        float4 pe = inb ? g_rpe[obase + g] : make_float4(0.f, 0.f, -1e30f, -1e30f);
        bool hit = (pe.x + pe.z >= xmin) && (pe.x - pe.z <= xmax) &&
                   (pe.y + pe.w >= ymin) && (pe.y - pe.w <= ymax);
        unsigned bal = __ballot_sync(0xffffffffu, hit);
        if (lane == 0) s_wcnt[wid] = __popc(bal);
        __syncthreads();
        if (tid == 0) {
            int s = 0;
            #pragma unroll
            for (int w = 0; w < 8; w++) { s_woff[w] = s; s += s_wcnt[w]; }
            s_total = s;
        }
        __syncthreads();
        if (hit) {
            int slot = s_woff[wid] + __popc(bal & ((1u << lane) - 1u));
            s_xy[slot] = make_float2(pe.x, pe.y);
            s_co[slot] = g_rco[obase + g];
            s_cl[slot] = g_rcl[obase + g];
        }
        __syncthreads();
        int cnt = s_total;

        if (alive) {
            for (int jj = 0; jj < cnt; jj++) {
                float2 xy = s_xy[jj];
                float4 co = s_co[jj];
                float dx = xy.x - pxf;
                float dy = xy.y - pyf;
                float power = -0.5f * (co.x*dx*dx + co.z*dy*dy) - co.y*dx*dy;
                if (power > 0.0f) continue;
                float raw = co.w * __expf(power);
                if (raw < (1.0f / 255.0f)) continue;
                float alpha = fminf(0.99f, raw);
                float4 cl = s_cl[jj];
                float wgt = alpha * T;
                ar += wgt * cl.x;
                ag += wgt * cl.y;
                ab += wgt * cl.z;
                T *= (1.0f - alpha);
                if (T < 1e-6f) { alive = false; break; }
            }
        }
        int nalive = __syncthreads_count(alive ? 1 : 0);
        if (nalive == 0) break;
    }

    int pid = pyi * WD + pxi;
    out[pid]           = ar + T * bg[0];
    out[HD*WD + pid]   = ag + T * bg[1];
    out[2*HD*WD + pid] = ab + T * bg[2];
}

// ---------------- launch ----------------
extern "C" void kernel_launch(void* const* d_in, const int* in_sizes, int n_in,
                              void* d_out, int out_size)
{
    const float* means  = (const float*)d_in[0];
    const float* cols   = (const float*)d_in[1];
    const float* ops    = (const float*)d_in[2];
    const float* scales = (const float*)d_in[3];
    const float* rots   = (const float*)d_in[4];
    const float* bg     = (const float*)d_in[5];
    const float* Vm     = (const float*)d_in[6];
    const float* Pr     = (const float*)d_in[7];
    float* out = (float*)d_out;

    cudaFuncSetAttribute(region_sort_kernel,
                         cudaFuncAttributeMaxDynamicSharedMemorySize, 65536);

    zero_kernel<<<1, 64>>>();
    preprocess_kernel<<<PN/256, 256>>>(means, cols, ops, scales, rots, Vm, Pr);
    region_sort_kernel<<<64, 256, 65536>>>();
    dim3 grid(WD/16, HD/16), block(16, 16);
    raster_kernel<<<grid, block>>>(bg, out);
}

// round 4
// speedup vs baseline: 1.6310x; 1.5646x over previous
#include <cuda_runtime.h>

// ---------------- problem constants ----------------
#define PN    8192
#define WD    256
#define HD    256
#define TANXc 0.5f
#define TANYc 0.5f
#define FXc   256.0f
#define FYc   256.0f
#define NTX   16          // tiles per row (16px tiles)
#define NTILE 256
#define TCAP  4096        // per-tile list capacity

typedef unsigned long long u64;

// ---------------- scratch ----------------
__device__ float4 g_pe_u[PN];            // mean2d.xy (zw unused post-binning)
__device__ float4 g_co_u[PN];            // conic A,B,C, opacity
__device__ float4 g_cl_u[PN];            // color
__device__ u64    g_tkey[NTILE * TCAP];  // per-tile unsorted keys
__device__ int    g_tcnt[NTILE];
__device__ float4 g_ta[NTILE * TCAP];    // sorted: x, y, A, B
__device__ float4 g_tb[NTILE * TCAP];    // sorted: C, o, r, g
__device__ float  g_tc[NTILE * TCAP];    // sorted: b

__global__ void zero_kernel() { g_tcnt[threadIdx.x] = 0; }

// ---------------- preprocess + direct per-tile binning ----------------
__global__ __launch_bounds__(256) void preprocess_kernel(
    const float* __restrict__ means, const float* __restrict__ cols,
    const float* __restrict__ ops, const float* __restrict__ scales,
    const float* __restrict__ rots, const float* __restrict__ Vm,
    const float* __restrict__ Pr)
{
    int i = blockIdx.x * blockDim.x + threadIdx.x;
    if (i >= PN) return;

    float mx = means[3*i+0], my = means[3*i+1], mz = means[3*i+2];

    float pv0 = mx*Vm[0] + my*Vm[4] + mz*Vm[8]  + Vm[12];
    float pv1 = mx*Vm[1] + my*Vm[5] + mz*Vm[9]  + Vm[13];
    float pv2 = mx*Vm[2] + my*Vm[6] + mz*Vm[10] + Vm[14];

    float ph0 = mx*Pr[0] + my*Pr[4] + mz*Pr[8]  + Pr[12];
    float ph1 = mx*Pr[1] + my*Pr[5] + mz*Pr[9]  + Pr[13];
    float ph3 = mx*Pr[3] + my*Pr[7] + mz*Pr[11] + Pr[15];
    float invw = 1.0f / (ph3 + 1e-7f);
    float m2x = ((ph0*invw + 1.0f) * (float)WD - 1.0f) * 0.5f;
    float m2y = ((ph1*invw + 1.0f) * (float)HD - 1.0f) * 0.5f;

    float qr = rots[4*i+0], qx = rots[4*i+1], qy = rots[4*i+2], qz = rots[4*i+3];
    float qn = sqrtf(qr*qr + qx*qx + qy*qy + qz*qz);
    qr /= qn; qx /= qn; qy /= qn; qz /= qn;
    float R[3][3];
    R[0][0] = 1.0f - 2.0f*(qy*qy + qz*qz); R[0][1] = 2.0f*(qx*qy - qr*qz); R[0][2] = 2.0f*(qx*qz + qr*qy);
    R[1][0] = 2.0f*(qx*qy + qr*qz); R[1][1] = 1.0f - 2.0f*(qx*qx + qz*qz); R[1][2] = 2.0f*(qy*qz - qr*qx);
    R[2][0] = 2.0f*(qx*qz - qr*qy); R[2][1] = 2.0f*(qy*qz + qr*qx); R[2][2] = 1.0f - 2.0f*(qx*qx + qy*qy);

    float s0 = scales[3*i+0], s1 = scales[3*i+1], s2 = scales[3*i+2];
    float sq0 = s0*s0, sq1 = s1*s1, sq2 = s2*s2;

    float Sg[3][3];
    #pragma unroll
    for (int r = 0; r < 3; r++)
        #pragma unroll
        for (int c = 0; c < 3; c++)
            Sg[r][c] = R[r][0]*sq0*R[c][0] + R[r][1]*sq1*R[c][1] + R[r][2]*sq2*R[c][2];

    float Mt[3][3], Cc[3][3];
    #pragma unroll
    for (int r = 0; r < 3; r++)
        #pragma unroll
        for (int k = 0; k < 3; k++)
            Mt[r][k] = Vm[0*4+r]*Sg[0][k] + Vm[1*4+r]*Sg[1][k] + Vm[2*4+r]*Sg[2][k];
    #pragma unroll
    for (int r = 0; r < 3; r++)
        #pragma unroll
        for (int l = 0; l < 3; l++)
            Cc[r][l] = Mt[r][0]*Vm[0*4+l] + Mt[r][1]*Vm[1*4+l] + Mt[r][2]*Vm[2*4+l];

    float tz  = pv2;
    float itz = 1.0f / tz;
    float limx = 1.3f * TANXc, limy = 1.3f * TANYc;
    float txc = fminf(limx, fmaxf(-limx, pv0*itz)) * tz;
    float tyc = fminf(limy, fmaxf(-limy, pv1*itz)) * tz;
    float J00 = FXc*itz, J02 = -FXc*txc*itz*itz;
    float J11 = FYc*itz, J12 = -FYc*tyc*itz*itz;

    float T00 = J00*Cc[0][0] + J02*Cc[2][0];
    float T01 = J00*Cc[0][1] + J02*Cc[2][1];
    float T02 = J00*Cc[0][2] + J02*Cc[2][2];
    float T11 = J11*Cc[1][1] + J12*Cc[2][1];
    float T12 = J11*Cc[1][2] + J12*Cc[2][2];
    float c00 = T00*J00 + T02*J02;
    float c01 = T01*J11 + T02*J12;
    float c11 = T11*J11 + T12*J12;

    float a = c00 + 0.3f, b = c01, c = c11 + 0.3f;
    float det  = a*c - b*b;
    float idet = 1.0f / det;
    float A  = c*idet, B = -b*idet, C2 = a*idet;

    float o   = ops[i];
    float tau = 2.0f * logf(255.0f * o);
    float tq  = fmaxf(tau, 0.0f);
    float ex  = sqrtf(tq * a) + 1.0f;
    float ey  = sqrtf(tq * c) + 1.0f;

    g_pe_u[i] = make_float4(m2x, m2y, 0.0f, 0.0f);
    g_co_u[i] = make_float4(A, B, C2, o);
    g_cl_u[i] = make_float4(cols[3*i+0], cols[3*i+1], cols[3*i+2], 0.0f);

    if (tau <= 0.0f) return;   // alpha can never reach 1/255

    // exact 16px-tile span of the AABB
    int rx0 = max(0,       (int)ceilf ((m2x - ex - 15.0f) * (1.0f / 16.0f)));
    int rx1 = min(NTX - 1, (int)floorf((m2x + ex)          * (1.0f / 16.0f)));
    int ry0 = max(0,       (int)ceilf ((m2y - ey - 15.0f) * (1.0f / 16.0f)));
    int ry1 = min(NTX - 1, (int)floorf((m2y + ey)          * (1.0f / 16.0f)));
    if (rx0 > rx1 || ry0 > ry1) return;

    u64 key = ((u64)__float_as_uint(pv2) << 32) | (unsigned)i;
    for (int ry = ry0; ry <= ry1; ry++)
        for (int rx = rx0; rx <= rx1; rx++) {
            int t = ry * NTX + rx;
            int pos = atomicAdd(&g_tcnt[t], 1);
            if (pos < TCAP) g_tkey[t * TCAP + pos] = key;
        }
}

// ---------------- per-tile depth sort (256 independent blocks) + gather ----------------
__global__ __launch_bounds__(256) void tile_sort_kernel()
{
    __shared__ u64 sk[TCAP];
    const int r = blockIdx.x;
    const int t = threadIdx.x;
    const int n = min(g_tcnt[r], TCAP);
    if (n == 0) return;

    int m = 2;
    while (m < n) m <<= 1;

    for (int i = t; i < m; i += 256)
        sk[i] = (i < n) ? g_tkey[r * TCAP + i] : ~0ull;
    __syncthreads();

    for (int k = 2; k <= m; k <<= 1) {
        for (int j = k >> 1; j > 0; j >>= 1) {
            for (int p = t; p < (m >> 1); p += 256) {
                int i  = ((p & ~(j - 1)) << 1) | (p & (j - 1));
                bool up = ((i & k) == 0);
                u64 x = sk[i], y = sk[i | j];
                if ((x > y) == up) { sk[i] = y; sk[i | j] = x; }
            }
            __syncthreads();
        }
    }

    for (int i = t; i < n; i += 256) {
        int s = (int)(sk[i] & 0xFFFFFFFFu);
        float4 pe = g_pe_u[s];
        float4 co = g_co_u[s];
        float4 cl = g_cl_u[s];
        g_ta[r * TCAP + i] = make_float4(pe.x, pe.y, co.x, co.y);
        g_tb[r * TCAP + i] = make_float4(co.z, co.w, cl.x, cl.y);
        g_tc[r * TCAP + i] = cl.z;
    }
}

// ---------------- tiled rasterizer: direct per-tile lists, no compaction ----------------
__global__ __launch_bounds__(256) void raster_kernel(const float* __restrict__ bg,
                                                     float* __restrict__ out)
{
    const int tx = threadIdx.x, ty = threadIdx.y;
    const int tid = ty * 16 + tx;
    const int pxi = blockIdx.x * 16 + tx;
    const int pyi = blockIdx.y * 16 + ty;
    const float pxf = (float)pxi, pyf = (float)pyi;

    const int r = (int)blockIdx.y * NTX + (int)blockIdx.x;
    const int n = min(g_tcnt[r], TCAP);
    const int obase = r * TCAP;

    __shared__ float4 s_a[256];   // x, y, A, B
    __shared__ float4 s_b[256];   // C, o, r, g
    __shared__ float  s_c[256];   // b

    float T = 1.0f;
    float ar = 0.0f, ag = 0.0f, ab = 0.0f;
    bool alive = true;

    for (int start = 0; start < n; start += 256) {
        int g = start + tid;
        if (g < n) {
            s_a[tid] = g_ta[obase + g];
            s_b[tid] = g_tb[obase + g];
            s_c[tid] = g_tc[obase + g];
        }
        __syncthreads();
        int cnt = min(256, n - start);

        if (alive) {
            for (int jj = 0; jj < cnt; jj++) {
                float4 ea = s_a[jj];
                float dx = ea.x - pxf;
                float dy = ea.y - pyf;
                float4 eb = s_b[jj];
                float power = -0.5f * (ea.z*dx*dx + eb.x*dy*dy) - ea.w*dx*dy;
                if (power > 0.0f) continue;
                float raw = eb.y * __expf(power);
                if (raw < (1.0f / 255.0f)) continue;
                float alpha = fminf(0.99f, raw);
                float wgt = alpha * T;
                ar += wgt * eb.z;
                ag += wgt * eb.w;
                ab += wgt * s_c[jj];
                T *= (1.0f - alpha);
                if (T < 1e-6f) { alive = false; break; }
            }
        }
        int nalive = __syncthreads_count(alive ? 1 : 0);
        if (nalive == 0) break;
    }

    int pid = pyi * WD + pxi;
    out[pid]           = ar + T * bg[0];
    out[HD*WD + pid]   = ag + T * bg[1];
    out[2*HD*WD + pid] = ab + T * bg[2];
}

// ---------------- launch ----------------
extern "C" void kernel_launch(void* const* d_in, const int* in_sizes, int n_in,
                              void* d_out, int out_size)
{
    const float* means  = (const float*)d_in[0];
    const float* cols   = (const float*)d_in[1];
    const float* ops    = (const float*)d_in[2];
    const float* scales = (const float*)d_in[3];
    const float* rots   = (const float*)d_in[4];
    const float* bg     = (const float*)d_in[5];
    const float* Vm     = (const float*)d_in[6];
    const float* Pr     = (const float*)d_in[7];
    float* out = (float*)d_out;

    zero_kernel<<<1, NTILE>>>();
    preprocess_kernel<<<PN/256, 256>>>(means, cols, ops, scales, rots, Vm, Pr);
    tile_sort_kernel<<<NTILE, 256>>>();
    dim3 grid(WD/16, HD/16), block(16, 16);
    raster_kernel<<<grid, block>>>(bg, out);
}

// round 5
// speedup vs baseline: 2.0780x; 1.2741x over previous
#include <cuda_runtime.h>

// ---------------- problem constants ----------------
#define PN    8192
#define WD    256
#define HD    256
#define TANXc 0.5f
#define TANYc 0.5f
#define FXc   256.0f
#define FYc   256.0f
#define TSZ   8           // tile size in px
#define NTX   32          // tiles per row
#define NTILE 1024
#define TCAP  1024        // per-tile list capacity

typedef unsigned long long u64;

// ---------------- scratch ----------------
__device__ float4 g_pe_u[PN];            // mean2d.xy
__device__ float4 g_co_u[PN];            // conic A,B,C, opacity
__device__ float4 g_cl_u[PN];            // color
__device__ u64    g_tkey[NTILE * TCAP];  // per-tile unsorted keys
__device__ int    g_tcnt[NTILE];
__device__ float4 g_ta[NTILE * TCAP];    // sorted: x, y, A, B
__device__ float4 g_tb[NTILE * TCAP];    // sorted: C, o, r, g
__device__ float  g_tc[NTILE * TCAP];    // sorted: b

__global__ void zero_kernel() { g_tcnt[threadIdx.x] = 0; }

// ---------------- preprocess + direct per-tile binning ----------------
__global__ __launch_bounds__(256) void preprocess_kernel(
    const float* __restrict__ means, const float* __restrict__ cols,
    const float* __restrict__ ops, const float* __restrict__ scales,
    const float* __restrict__ rots, const float* __restrict__ Vm,
    const float* __restrict__ Pr)
{
    int i = blockIdx.x * blockDim.x + threadIdx.x;
    if (i >= PN) return;

    float mx = means[3*i+0], my = means[3*i+1], mz = means[3*i+2];

    float pv0 = mx*Vm[0] + my*Vm[4] + mz*Vm[8]  + Vm[12];
    float pv1 = mx*Vm[1] + my*Vm[5] + mz*Vm[9]  + Vm[13];
    float pv2 = mx*Vm[2] + my*Vm[6] + mz*Vm[10] + Vm[14];

    float ph0 = mx*Pr[0] + my*Pr[4] + mz*Pr[8]  + Pr[12];
    float ph1 = mx*Pr[1] + my*Pr[5] + mz*Pr[9]  + Pr[13];
    float ph3 = mx*Pr[3] + my*Pr[7] + mz*Pr[11] + Pr[15];
    float invw = 1.0f / (ph3 + 1e-7f);
    float m2x = ((ph0*invw + 1.0f) * (float)WD - 1.0f) * 0.5f;
    float m2y = ((ph1*invw + 1.0f) * (float)HD - 1.0f) * 0.5f;

    float qr = rots[4*i+0], qx = rots[4*i+1], qy = rots[4*i+2], qz = rots[4*i+3];
    float qn = sqrtf(qr*qr + qx*qx + qy*qy + qz*qz);
    qr /= qn; qx /= qn; qy /= qn; qz /= qn;
    float R[3][3];
    R[0][0] = 1.0f - 2.0f*(qy*qy + qz*qz); R[0][1] = 2.0f*(qx*qy - qr*qz); R[0][2] = 2.0f*(qx*qz + qr*qy);
    R[1][0] = 2.0f*(qx*qy + qr*qz); R[1][1] = 1.0f - 2.0f*(qx*qx + qz*qz); R[1][2] = 2.0f*(qy*qz - qr*qx);
    R[2][0] = 2.0f*(qx*qz - qr*qy); R[2][1] = 2.0f*(qy*qz + qr*qx); R[2][2] = 1.0f - 2.0f*(qx*qx + qy*qy);

    float s0 = scales[3*i+0], s1 = scales[3*i+1], s2 = scales[3*i+2];
    float sq0 = s0*s0, sq1 = s1*s1, sq2 = s2*s2;

    float Sg[3][3];
    #pragma unroll
    for (int r = 0; r < 3; r++)
        #pragma unroll
        for (int c = 0; c < 3; c++)
            Sg[r][c] = R[r][0]*sq0*R[c][0] + R[r][1]*sq1*R[c][1] + R[r][2]*sq2*R[c][2];

    float Mt[3][3], Cc[3][3];
    #pragma unroll
    for (int r = 0; r < 3; r++)
        #pragma unroll
        for (int k = 0; k < 3; k++)
            Mt[r][k] = Vm[0*4+r]*Sg[0][k] + Vm[1*4+r]*Sg[1][k] + Vm[2*4+r]*Sg[2][k];
    #pragma unroll
    for (int r = 0; r < 3; r++)
        #pragma unroll
        for (int l = 0; l < 3; l++)
            Cc[r][l] = Mt[r][0]*Vm[0*4+l] + Mt[r][1]*Vm[1*4+l] + Mt[r][2]*Vm[2*4+l];

    float tz  = pv2;
    float itz = 1.0f / tz;
    float limx = 1.3f * TANXc, limy = 1.3f * TANYc;
    float txc = fminf(limx, fmaxf(-limx, pv0*itz)) * tz;
    float tyc = fminf(limy, fmaxf(-limy, pv1*itz)) * tz;
    float J00 = FXc*itz, J02 = -FXc*txc*itz*itz;
    float J11 = FYc*itz, J12 = -FYc*tyc*itz*itz;

    float T00 = J00*Cc[0][0] + J02*Cc[2][0];
    float T01 = J00*Cc[0][1] + J02*Cc[2][1];
    float T02 = J00*Cc[0][2] + J02*Cc[2][2];
    float T11 = J11*Cc[1][1] + J12*Cc[2][1];
    float T12 = J11*Cc[1][2] + J12*Cc[2][2];
    float c00 = T00*J00 + T02*J02;
    float c01 = T01*J11 + T02*J12;
    float c11 = T11*J11 + T12*J12;

    float a = c00 + 0.3f, b = c01, c = c11 + 0.3f;
    float det  = a*c - b*b;
    float idet = 1.0f / det;
    float A  = c*idet, B = -b*idet, C2 = a*idet;

    float o   = ops[i];
    float tau = 2.0f * logf(255.0f * o);
    float tq  = fmaxf(tau, 0.0f);
    float ex  = sqrtf(tq * a) + 1.0f;
    float ey  = sqrtf(tq * c) + 1.0f;

    g_pe_u[i] = make_float4(m2x, m2y, 0.0f, 0.0f);
    g_co_u[i] = make_float4(A, B, C2, o);
    g_cl_u[i] = make_float4(cols[3*i+0], cols[3*i+1], cols[3*i+2], 0.0f);

    if (tau <= 0.0f) return;   // alpha can never reach 1/255

    // exact TSZ-px tile span of the AABB
    const float inv = 1.0f / (float)TSZ;
    int rx0 = max(0,       (int)ceilf ((m2x - ex - (float)(TSZ-1)) * inv));
    int rx1 = min(NTX - 1, (int)floorf((m2x + ex) * inv));
    int ry0 = max(0,       (int)ceilf ((m2y - ey - (float)(TSZ-1)) * inv));
    int ry1 = min(NTX - 1, (int)floorf((m2y + ey) * inv));
    if (rx0 > rx1 || ry0 > ry1) return;

    u64 key = ((u64)__float_as_uint(pv2) << 32) | (unsigned)i;
    for (int ry = ry0; ry <= ry1; ry++)
        for (int rx = rx0; rx <= rx1; rx++) {
            int t = ry * NTX + rx;
            int pos = atomicAdd(&g_tcnt[t], 1);
            if (pos < TCAP) g_tkey[t * TCAP + pos] = key;
        }
}

// ---------------- per-tile depth sort (1024 independent blocks) + gather ----------------
__global__ __launch_bounds__(128) void tile_sort_kernel()
{
    __shared__ u64 sk[TCAP];
    const int r = blockIdx.x;
    const int t = threadIdx.x;
    const int n = min(g_tcnt[r], TCAP);
    if (n == 0) return;

    int m = 2;
    while (m < n) m <<= 1;

    for (int i = t; i < m; i += 128)
        sk[i] = (i < n) ? g_tkey[r * TCAP + i] : ~0ull;
    __syncthreads();

    for (int k = 2; k <= m; k <<= 1) {
        for (int j = k >> 1; j > 0; j >>= 1) {
            for (int p = t; p < (m >> 1); p += 128) {
                int i  = ((p & ~(j - 1)) << 1) | (p & (j - 1));
                bool up = ((i & k) == 0);
                u64 x = sk[i], y = sk[i | j];
                if ((x > y) == up) { sk[i] = y; sk[i | j] = x; }
            }
            __syncthreads();
        }
    }

    for (int i = t; i < n; i += 128) {
        int s = (int)(sk[i] & 0xFFFFFFFFu);
        float4 pe = g_pe_u[s];
        float4 co = g_co_u[s];
        float4 cl = g_cl_u[s];
        g_ta[r * TCAP + i] = make_float4(pe.x, pe.y, co.x, co.y);
        g_tb[r * TCAP + i] = make_float4(co.z, co.w, cl.x, cl.y);
        g_tc[r * TCAP + i] = cl.z;
    }
}

// ---------------- tiled rasterizer: 8x8 tiles, 64 threads, no compaction ----------------
__global__ __launch_bounds__(64) void raster_kernel(const float* __restrict__ bg,
                                                    float* __restrict__ out)
{
    const int tx = threadIdx.x, ty = threadIdx.y;
    const int tid = ty * TSZ + tx;
    const int pxi = blockIdx.x * TSZ + tx;
    const int pyi = blockIdx.y * TSZ + ty;
    const float pxf = (float)pxi, pyf = (float)pyi;

    const int r = (int)blockIdx.y * NTX + (int)blockIdx.x;
    const int n = min(g_tcnt[r], TCAP);
    const int obase = r * TCAP;

    __shared__ float4 s_a[64];   // x, y, A, B
    __shared__ float4 s_b[64];   // C, o, r, g
    __shared__ float  s_c[64];   // b

    float T = 1.0f;
    float ar = 0.0f, ag = 0.0f, ab = 0.0f;
    bool alive = true;

    for (int start = 0; start < n; start += 64) {
        int g = start + tid;
        if (g < n) {
            s_a[tid] = g_ta[obase + g];
            s_b[tid] = g_tb[obase + g];
            s_c[tid] = g_tc[obase + g];
        }
        __syncthreads();
        int cnt = min(64, n - start);

        if (alive) {
            #pragma unroll 2
            for (int jj = 0; jj < cnt; jj++) {
                float4 ea = s_a[jj];
                float dx = ea.x - pxf;
                float dy = ea.y - pyf;
                float4 eb = s_b[jj];
                float power = -0.5f * (ea.z*dx*dx + eb.x*dy*dy) - ea.w*dx*dy;
                if (power > 0.0f) continue;
                float raw = eb.y * __expf(power);
                if (raw < (1.0f / 255.0f)) continue;
                float alpha = fminf(0.99f, raw);
                float wgt = alpha * T;
                ar += wgt * eb.z;
                ag += wgt * eb.w;
                ab += wgt * s_c[jj];
                T *= (1.0f - alpha);
                if (T < 1e-6f) { alive = false; break; }
            }
        }
        int nalive = __syncthreads_count(alive ? 1 : 0);
        if (nalive == 0) break;
    }

    int pid = pyi * WD + pxi;
    out[pid]           = ar + T * bg[0];
    out[HD*WD + pid]   = ag + T * bg[1];
    out[2*HD*WD + pid] = ab + T * bg[2];
}

// ---------------- launch ----------------
extern "C" void kernel_launch(void* const* d_in, const int* in_sizes, int n_in,
                              void* d_out, int out_size)
{
    const float* means  = (const float*)d_in[0];
    const float* cols   = (const float*)d_in[1];
    const float* ops    = (const float*)d_in[2];
    const float* scales = (const float*)d_in[3];
    const float* rots   = (const float*)d_in[4];
    const float* bg     = (const float*)d_in[5];
    const float* Vm     = (const float*)d_in[6];
    const float* Pr     = (const float*)d_in[7];
    float* out = (float*)d_out;

    zero_kernel<<<1, NTILE>>>();
    preprocess_kernel<<<PN/256, 256>>>(means, cols, ops, scales, rots, Vm, Pr);
    tile_sort_kernel<<<NTILE, 128>>>();
    dim3 grid(WD/TSZ, HD/TSZ), block(TSZ, TSZ);
    raster_kernel<<<grid, block>>>(bg, out);
}

// round 6
// speedup vs baseline: 2.2854x; 1.0998x over previous
#include <cuda_runtime.h>

// ---------------- problem constants ----------------
#define PN    8192
#define WD    256
#define HD    256
#define TANXc 0.5f
#define TANYc 0.5f
#define FXc   256.0f
#define FYc   256.0f
#define TSZ   8           // tile size in px
#define NTX   32          // tiles per row
#define NTILE 1024
#define TCAP  1024        // per-tile list capacity

typedef unsigned long long u64;

// ---------------- scratch ----------------
__device__ float4 g_pe_u[PN];            // mean2d.xy
__device__ float4 g_co_u[PN];            // conic A,B,C, opacity
__device__ float4 g_cl_u[PN];            // color
__device__ u64    g_tkey[NTILE * TCAP];  // per-tile unsorted keys
__device__ int    g_tcnt[NTILE];         // atomic counters (reset by tile_sort each pass)
__device__ int    g_scnt[NTILE];         // stable counts for raster
__device__ float4 g_ta[NTILE * TCAP];    // sorted: x, y, A, B
__device__ float4 g_tb[NTILE * TCAP];    // sorted: C, o, r, g
__device__ float  g_tc[NTILE * TCAP];    // sorted: b

// ---------------- preprocess + direct per-tile binning ----------------
__global__ __launch_bounds__(128) void preprocess_kernel(
    const float* __restrict__ means, const float* __restrict__ cols,
    const float* __restrict__ ops, const float* __restrict__ scales,
    const float* __restrict__ rots, const float* __restrict__ Vm,
    const float* __restrict__ Pr)
{
    int i = blockIdx.x * blockDim.x + threadIdx.x;
    if (i >= PN) return;

    float mx = means[3*i+0], my = means[3*i+1], mz = means[3*i+2];

    float pv0 = mx*Vm[0] + my*Vm[4] + mz*Vm[8]  + Vm[12];
    float pv1 = mx*Vm[1] + my*Vm[5] + mz*Vm[9]  + Vm[13];
    float pv2 = mx*Vm[2] + my*Vm[6] + mz*Vm[10] + Vm[14];

    float ph0 = mx*Pr[0] + my*Pr[4] + mz*Pr[8]  + Pr[12];
    float ph1 = mx*Pr[1] + my*Pr[5] + mz*Pr[9]  + Pr[13];
    float ph3 = mx*Pr[3] + my*Pr[7] + mz*Pr[11] + Pr[15];
    float invw = 1.0f / (ph3 + 1e-7f);
    float m2x = ((ph0*invw + 1.0f) * (float)WD - 1.0f) * 0.5f;
    float m2y = ((ph1*invw + 1.0f) * (float)HD - 1.0f) * 0.5f;

    float qr = rots[4*i+0], qx = rots[4*i+1], qy = rots[4*i+2], qz = rots[4*i+3];
    float qn = sqrtf(qr*qr + qx*qx + qy*qy + qz*qz);
    qr /= qn; qx /= qn; qy /= qn; qz /= qn;
    float R[3][3];
    R[0][0] = 1.0f - 2.0f*(qy*qy + qz*qz); R[0][1] = 2.0f*(qx*qy - qr*qz); R[0][2] = 2.0f*(qx*qz + qr*qy);
    R[1][0] = 2.0f*(qx*qy + qr*qz); R[1][1] = 1.0f - 2.0f*(qx*qx + qz*qz); R[1][2] = 2.0f*(qy*qz - qr*qx);
    R[2][0] = 2.0f*(qx*qz - qr*qy); R[2][1] = 2.0f*(qy*qz + qr*qx); R[2][2] = 1.0f - 2.0f*(qx*qx + qy*qy);

    float s0 = scales[3*i+0], s1 = scales[3*i+1], s2 = scales[3*i+2];
    float sq0 = s0*s0, sq1 = s1*s1, sq2 = s2*s2;

    float Sg[3][3];
    #pragma unroll
    for (int r = 0; r < 3; r++)
        #pragma unroll
        for (int c = 0; c < 3; c++)
            Sg[r][c] = R[r][0]*sq0*R[c][0] + R[r][1]*sq1*R[c][1] + R[r][2]*sq2*R[c][2];

    float Mt[3][3], Cc[3][3];
    #pragma unroll
    for (int r = 0; r < 3; r++)
        #pragma unroll
        for (int k = 0; k < 3; k++)
            Mt[r][k] = Vm[0*4+r]*Sg[0][k] + Vm[1*4+r]*Sg[1][k] + Vm[2*4+r]*Sg[2][k];
    #pragma unroll
    for (int r = 0; r < 3; r++)
        #pragma unroll
        for (int l = 0; l < 3; l++)
            Cc[r][l] = Mt[r][0]*Vm[0*4+l] + Mt[r][1]*Vm[1*4+l] + Mt[r][2]*Vm[2*4+l];

    float tz  = pv2;
    float itz = 1.0f / tz;
    float limx = 1.3f * TANXc, limy = 1.3f * TANYc;
    float txc = fminf(limx, fmaxf(-limx, pv0*itz)) * tz;
    float tyc = fminf(limy, fmaxf(-limy, pv1*itz)) * tz;
    float J00 = FXc*itz, J02 = -FXc*txc*itz*itz;
    float J11 = FYc*itz, J12 = -FYc*tyc*itz*itz;

    float T00 = J00*Cc[0][0] + J02*Cc[2][0];
    float T01 = J00*Cc[0][1] + J02*Cc[2][1];
    float T02 = J00*Cc[0][2] + J02*Cc[2][2];
    float T11 = J11*Cc[1][1] + J12*Cc[2][1];
    float T12 = J11*Cc[1][2] + J12*Cc[2][2];
    float c00 = T00*J00 + T02*J02;
    float c01 = T01*J11 + T02*J12;
    float c11 = T11*J11 + T12*J12;

    float a = c00 + 0.3f, b = c01, c = c11 + 0.3f;
    float det  = a*c - b*b;
    float idet = 1.0f / det;
    float A  = c*idet, B = -b*idet, C2 = a*idet;

    float o   = ops[i];
    float tau = 2.0f * logf(255.0f * o);
    float tq  = fmaxf(tau, 0.0f);
    float ex  = sqrtf(tq * a) + 1.0f;
    float ey  = sqrtf(tq * c) + 1.0f;

    g_pe_u[i] = make_float4(m2x, m2y, 0.0f, 0.0f);
    g_co_u[i] = make_float4(A, B, C2, o);
    g_cl_u[i] = make_float4(cols[3*i+0], cols[3*i+1], cols[3*i+2], 0.0f);

    if (tau <= 0.0f) return;   // alpha can never reach 1/255

    // exact TSZ-px tile span of the AABB
    const float inv = 1.0f / (float)TSZ;
    int rx0 = max(0,       (int)ceilf ((m2x - ex - (float)(TSZ-1)) * inv));
    int rx1 = min(NTX - 1, (int)floorf((m2x + ex) * inv));
    int ry0 = max(0,       (int)ceilf ((m2y - ey - (float)(TSZ-1)) * inv));
    int ry1 = min(NTX - 1, (int)floorf((m2y + ey) * inv));
    if (rx0 > rx1 || ry0 > ry1) return;

    u64 key = ((u64)__float_as_uint(pv2) << 32) | (unsigned)i;
    for (int ry = ry0; ry <= ry1; ry++)
        for (int rx = rx0; rx <= rx1; rx++) {
            int t = ry * NTX + rx;
            int pos = atomicAdd(&g_tcnt[t], 1);
            if (pos < TCAP) g_tkey[t * TCAP + pos] = key;
        }
}

// ---------------- per-tile depth sort (1024 independent blocks) + gather + counter reset ----------------
__global__ __launch_bounds__(128) void tile_sort_kernel()
{
    __shared__ u64 sk[TCAP];
    const int r = blockIdx.x;
    const int t = threadIdx.x;
    const int n = min(g_tcnt[r], TCAP);
    if (t == 0) {
        g_scnt[r] = n;
        g_tcnt[r] = 0;          // reset for next graph replay
    }
    if (n == 0) return;

    int m = 2;
    while (m < n) m <<= 1;

    for (int i = t; i < m; i += 128)
        sk[i] = (i < n) ? g_tkey[r * TCAP + i] : ~0ull;
    __syncthreads();

    for (int k = 2; k <= m; k <<= 1) {
        for (int j = k >> 1; j > 0; j >>= 1) {
            for (int p = t; p < (m >> 1); p += 128) {
                int i  = ((p & ~(j - 1)) << 1) | (p & (j - 1));
                bool up = ((i & k) == 0);
                u64 x = sk[i], y = sk[i | j];
                if ((x > y) == up) { sk[i] = y; sk[i | j] = x; }
            }
            __syncthreads();
        }
    }

    for (int i = t; i < n; i += 128) {
        int s = (int)(sk[i] & 0xFFFFFFFFu);
        float4 pe = g_pe_u[s];
        float4 co = g_co_u[s];
        float4 cl = g_cl_u[s];
        g_ta[r * TCAP + i] = make_float4(pe.x, pe.y, co.x, co.y);
        g_tb[r * TCAP + i] = make_float4(co.z, co.w, cl.x, cl.y);
        g_tc[r * TCAP + i] = cl.z;
    }
}

// ---------------- tiled rasterizer: 8x8 tiles, software-pipelined blend ----------------
__global__ __launch_bounds__(64) void raster_kernel(const float* __restrict__ bg,
                                                    float* __restrict__ out)
{
    const int tx = threadIdx.x, ty = threadIdx.y;
    const int tid = ty * TSZ + tx;
    const int pxi = blockIdx.x * TSZ + tx;
    const int pyi = blockIdx.y * TSZ + ty;
    const float pxf = (float)pxi, pyf = (float)pyi;

    const int r = (int)blockIdx.y * NTX + (int)blockIdx.x;
    const int n = g_scnt[r];
    const int obase = r * TCAP;

    __shared__ float4 s_a[64];   // x, y, A, B
    __shared__ float4 s_b[64];   // C, o, r, g
    __shared__ float  s_c[64];   // b

    float T = 1.0f;
    float ar = 0.0f, ag = 0.0f, ab = 0.0f;
    bool alive = true;

    for (int start = 0; start < n; start += 64) {
        int g = start + tid;
        if (g < n) {
            s_a[tid] = g_ta[obase + g];
            s_b[tid] = g_tb[obase + g];
            s_c[tid] = g_tc[obase + g];
        }
        __syncthreads();
        int cnt = min(64, n - start);

        if (alive) {
            // software-pipelined: prefetch entry jj+1 while blending jj
            float4 na = s_a[0];
            float4 nb = s_b[0];
            float  nc = s_c[0];
            #pragma unroll 2
            for (int jj = 0; jj < cnt; jj++) {
                float4 ea = na;
                float4 eb = nb;
                float  ec = nc;
                int j1 = jj + 1;
                if (j1 < cnt) { na = s_a[j1]; nb = s_b[j1]; nc = s_c[j1]; }

                float dx = ea.x - pxf;
                float dy = ea.y - pyf;
                float power = -0.5f * (ea.z*dx*dx + eb.x*dy*dy) - ea.w*dx*dy;
                float raw = eb.y * __expf(power);     // unconditional; discarded if power>0
                if (power > 0.0f || raw < (1.0f / 255.0f)) continue;
                float alpha = fminf(0.99f, raw);
                float wgt = alpha * T;
                ar += wgt * eb.z;
                ag += wgt * eb.w;
                ab += wgt * ec;
                T *= (1.0f - alpha);
                if (T < 1e-6f) { alive = false; break; }
            }
        }
        int nalive = __syncthreads_count(alive ? 1 : 0);
        if (nalive == 0) break;
    }

    int pid = pyi * WD + pxi;
    out[pid]           = ar + T * bg[0];
    out[HD*WD + pid]   = ag + T * bg[1];
    out[2*HD*WD + pid] = ab + T * bg[2];
}

// ---------------- launch ----------------
extern "C" void kernel_launch(void* const* d_in, const int* in_sizes, int n_in,
                              void* d_out, int out_size)
{
    const float* means  = (const float*)d_in[0];
    const float* cols   = (const float*)d_in[1];
    const float* ops    = (const float*)d_in[2];
    const float* scales = (const float*)d_in[3];
    const float* rots   = (const float*)d_in[4];
    const float* bg     = (const float*)d_in[5];
    const float* Vm     = (const float*)d_in[6];
    const float* Pr     = (const float*)d_in[7];
    float* out = (float*)d_out;

    preprocess_kernel<<<PN/128, 128>>>(means, cols, ops, scales, rots, Vm, Pr);
    tile_sort_kernel<<<NTILE, 128>>>();
    dim3 grid(WD/TSZ, HD/TSZ), block(TSZ, TSZ);
    raster_kernel<<<grid, block>>>(bg, out);
}